// round 10
// baseline (speedup 1.0000x reference)
#include <cuda_runtime.h>

// ---- problem constants ----
#define NROWS   8192      // N * OH * OW = 8*32*32
#define IDIM    72        // IC*KH*KW
#define OCH     16
#define NP      5
#define RKU     26        // u64 entries per record: l2, negz*5, alpha'*5, G*15
#define RECF    52        // floats per record in global (= RKU*2) = 13 uint4
#define RECS    60        // smem float stride: og*60%32 distinct -> conflict-free
#define ROWSB   64        // rows per CTA
#define RPT     4         // rows per thread
#define ISPLIT  6
#define IQ      12        // IDIM / ISPLIT

// global param table: [i][og][RECF] floats, og = o>>1, float2-interleaved over lane=o&1
__device__ float g_params[IDIM * 8 * RECF];
// partial sums: [split][row][og] -> float4(m.lo, m.hi, q.lo, q.hi)
__device__ float4 g_part[ISPLIT * NROWS * 8];

typedef unsigned long long u64;

// ---------------- packed f32x2 + fast-math helpers ----------------
__device__ __forceinline__ u64 pk2(unsigned lo, unsigned hi) {
    u64 d; asm("mov.b64 %0,{%1,%2};" : "=l"(d) : "r"(lo), "r"(hi)); return d;
}
__device__ __forceinline__ void upk(u64 v, unsigned& lo, unsigned& hi) {
    asm("mov.b64 {%0,%1},%2;" : "=r"(lo), "=r"(hi) : "l"(v));
}
__device__ __forceinline__ u64 bc(float f) {
    unsigned u = __float_as_uint(f); return pk2(u, u);
}
__device__ __forceinline__ u64 f2fma(u64 a, u64 b, u64 c) {
    u64 d; asm("fma.rn.f32x2 %0,%1,%2,%3;" : "=l"(d) : "l"(a), "l"(b), "l"(c)); return d;
}
__device__ __forceinline__ u64 f2mul(u64 a, u64 b) {
    u64 d; asm("mul.rn.f32x2 %0,%1,%2;" : "=l"(d) : "l"(a), "l"(b)); return d;
}
__device__ __forceinline__ u64 f2add(u64 a, u64 b) {
    u64 d; asm("add.rn.f32x2 %0,%1,%2;" : "=l"(d) : "l"(a), "l"(b)); return d;
}
__device__ __forceinline__ float ex2f(float x) {
    float y; asm("ex2.approx.f32 %0,%1;" : "=f"(y) : "f"(x)); return y;
}
__device__ __forceinline__ float lg2f(float x) {
    float y; asm("lg2.approx.f32 %0,%1;" : "=f"(y) : "f"(x)); return y;
}
__device__ __forceinline__ float rcpf(float x) {
    float y; asm("rcp.approx.f32 %0,%1;" : "=f"(y) : "f"(x)); return y;
}
// fp64 reciprocal: MUFU seed + 2 fp64 Newton steps (~1e-16 rel)
__device__ __forceinline__ double drcp(double d) {
    double r = (double)rcpf((float)d);
    r = r * (2.0 - d * r);
    r = r * (2.0 - d * r);
    return r;
}

// ---------------- precompute: shallow fp64 Schur/cofactor inverse ----------------
__global__ void gp_pre(const float* __restrict__ z,
                       const float* __restrict__ h,
                       const float* __restrict__ raw_l) {
    int pid = blockIdx.x * blockDim.x + threadIdx.x;
    if (pid >= IDIM * OCH) return;
    int o = pid / IDIM, i = pid - o * IDIM;
    int oi = o * IDIM + i;

    // softplus via MUFU: sp = ln2 * lg2(1 + 2^(x*log2e))
    float x   = raw_l[oi];
    float tx  = ex2f(x * 1.4426950408889634f);
    float spf = 0.6931471805599453f * lg2f(1.0f + tx);
    float l2f = spf * spf;
    float cK  = -0.7213475204444817f * rcpf(l2f);   // -log2e/(2 l2)
    double l2d = (double)l2f, spd = (double)spf;

    float zz[NP]; double hd[NP];
#pragma unroll
    for (int p = 0; p < NP; ++p) {
        zz[p] = z[oi * NP + p];
        hd[p] = (double)h[oi * NP + p];
    }

    // K formed with fp32 ex2 (2ulp, validated safe), held in fp64
    double Kd[NP][NP];
#pragma unroll
    for (int p = 0; p < NP; ++p)
#pragma unroll
        for (int q = 0; q < NP; ++q) {
            float dz = zz[p] - zz[q];
            double v = (double)ex2f(dz * dz * cK);
            if (p == q) v += 1e-4;
            Kd[p][q] = v;
        }

    // ---- 4x4 cofactor inverse of A = Kd[0..3][0..3] (shallow, parallel) ----
#define M_(r, c) Kd[r][c]
    double s0 = M_(0,0)*M_(1,1) - M_(1,0)*M_(0,1);
    double s1 = M_(0,0)*M_(1,2) - M_(1,0)*M_(0,2);
    double s2 = M_(0,0)*M_(1,3) - M_(1,0)*M_(0,3);
    double s3 = M_(0,1)*M_(1,2) - M_(1,1)*M_(0,2);
    double s4 = M_(0,1)*M_(1,3) - M_(1,1)*M_(0,3);
    double s5 = M_(0,2)*M_(1,3) - M_(1,2)*M_(0,3);
    double c5 = M_(2,2)*M_(3,3) - M_(3,2)*M_(2,3);
    double c4 = M_(2,1)*M_(3,3) - M_(3,1)*M_(2,3);
    double c3 = M_(2,1)*M_(3,2) - M_(3,1)*M_(2,2);
    double c2 = M_(2,0)*M_(3,3) - M_(3,0)*M_(2,3);
    double c1 = M_(2,0)*M_(3,2) - M_(3,0)*M_(2,2);
    double c0 = M_(2,0)*M_(3,1) - M_(3,0)*M_(2,1);
    double det = s0*c5 - s1*c4 + s2*c3 + s3*c2 - s4*c1 + s5*c0;
    double rd = drcp(det);      // det > 0 (SPD principal minor)

    double Ai[4][4];
    Ai[0][0] = ( M_(1,1)*c5 - M_(1,2)*c4 + M_(1,3)*c3) * rd;
    Ai[0][1] = (-M_(0,1)*c5 + M_(0,2)*c4 - M_(0,3)*c3) * rd;
    Ai[0][2] = ( M_(3,1)*s5 - M_(3,2)*s4 + M_(3,3)*s3) * rd;
    Ai[0][3] = (-M_(2,1)*s5 + M_(2,2)*s4 - M_(2,3)*s3) * rd;
    Ai[1][1] = ( M_(0,0)*c5 - M_(0,2)*c2 + M_(0,3)*c1) * rd;
    Ai[1][2] = (-M_(3,0)*s5 + M_(3,2)*s2 - M_(3,3)*s1) * rd;
    Ai[1][3] = ( M_(2,0)*s5 - M_(2,2)*s2 + M_(2,3)*s1) * rd;
    Ai[2][2] = ( M_(3,0)*s4 - M_(3,1)*s2 + M_(3,3)*s0) * rd;
    Ai[2][3] = (-M_(2,0)*s4 + M_(2,1)*s2 - M_(2,3)*s0) * rd;
    Ai[3][3] = ( M_(2,0)*s3 - M_(2,1)*s1 + M_(2,2)*s0) * rd;
    Ai[1][0] = Ai[0][1]; Ai[2][0] = Ai[0][2]; Ai[3][0] = Ai[0][3];
    Ai[2][1] = Ai[1][2]; Ai[3][1] = Ai[1][3]; Ai[3][2] = Ai[2][3];
#undef M_

    // ---- Schur complement: K = [[A, w],[w^T, c]] ----
    double u4[4];
#pragma unroll
    for (int j = 0; j < 4; ++j)
        u4[j] = Ai[j][0]*Kd[0][4] + Ai[j][1]*Kd[1][4]
              + Ai[j][2]*Kd[2][4] + Ai[j][3]*Kd[3][4];
    double schur = Kd[4][4] - (u4[0]*Kd[0][4] + u4[1]*Kd[1][4]
                             + u4[2]*Kd[2][4] + u4[3]*Kd[3][4]);
    double is = drcp(schur);    // schur >= lambda_min(K) >= 1e-4

    double Kinv[NP][NP];
#pragma unroll
    for (int j = 0; j < 4; ++j)
#pragma unroll
        for (int k = 0; k < 4; ++k) if (k >= j)
            Kinv[j][k] = Ai[j][k] + is * u4[j] * u4[k];
#pragma unroll
    for (int j = 0; j < 4; ++j) Kinv[j][4] = -is * u4[j];
    Kinv[4][4] = is;
#pragma unroll
    for (int j = 0; j < NP; ++j)
#pragma unroll
        for (int k = 0; k < NP; ++k) if (k < j) Kinv[j][k] = Kinv[k][j];

    // alpha = Kinv h (fp64 exact enough: eps64 * cond)
    double al[NP];
#pragma unroll
    for (int p = 0; p < NP; ++p) {
        double s = 0.0;
#pragma unroll
        for (int q = 0; q < NP; ++q) s = fma(Kinv[p][q], hd[q], s);
        al[p] = s;
    }

    // record (float2-interleaved): l2, -z*5, (l*alpha)*5, G*15
    // G[p][q] (q<=p): diag l2*Kinv[p][p], offdiag 2*l2*Kinv[q][p]
    int og = o >> 1, lane = o & 1;
    float* rec = g_params + (i * 8 + og) * RECF + lane;
    rec[0] = l2f;
#pragma unroll
    for (int p = 0; p < NP; ++p) rec[(1 + p) * 2] = -zz[p];
#pragma unroll
    for (int p = 0; p < NP; ++p) rec[(6 + p) * 2] = (float)(spd * al[p]);
#pragma unroll
    for (int p = 0; p < NP; ++p)
#pragma unroll
        for (int q = 0; q < NP; ++q) if (q <= p) {
            double g = l2d * Kinv[q][p];
            if (q != p) g += g;
            rec[(11 + p * (p + 1) / 2 + q) * 2] = (float)g;
        }
}

// ---------------- main: 6-way i-split, 4 rows/thread, EX2-based exps ----------------
__global__ __launch_bounds__(128) void gp_main(const float* __restrict__ xm,
                                               const float* __restrict__ xv) {
    __shared__ __align__(16) float2 ms_sm[IQ][ROWSB + 1];   // (mu, s2)
    __shared__ __align__(16) float  prm[IQ * 8 * RECS];

    const int tid   = threadIdx.x;
    const int row0  = blockIdx.x * ROWSB;
    const int split = blockIdx.y;
    const int i0    = split * IQ;

    // stage im2col(mu,s2) for this CTA's rows, this split's i-range
    for (int idx = tid; idx < IQ * ROWSB; idx += 128) {
        int il = idx >> 6, rlocal = idx & 63;
        int i = i0 + il;
        int c = i / 9, rem = i - c * 9;
        int kh = rem / 3, kw = rem - kh * 3;
        int r = row0 + rlocal;
        int n = r >> 10, oh = (r >> 5) & 31, ow = r & 31;
        int ih = oh + kh - 1, iw = ow + kw - 1;
        float m = 0.0f, v = 0.0f;
        if ((unsigned)ih < 32u && (unsigned)iw < 32u) {
            int g = ((n * 32 + ih) * 32 + iw) * 8 + c;
            m = xm[g]; v = xv[g];
        }
        ms_sm[il][rlocal] = make_float2(m, v);
    }
    // stage this split's param records: IQ x 8 x 13 uint4, contiguous in global
    {
        const uint4* src = reinterpret_cast<const uint4*>(g_params + i0 * 8 * RECF);
        for (int idx = tid; idx < IQ * 8 * 13; idx += 128) {
            int rrec = idx / 13, k4 = idx - rrec * 13;
            uint4 v4 = src[idx];
            *reinterpret_cast<uint4*>(&prm[rrec * RECS + 4 * k4]) = v4;
        }
    }
    __syncthreads();

    const int og = tid & 7;          // 8 o-pairs
    const int rp = tid >> 3;         // 16 row-quads -> rows rp*4 .. rp*4+3

    const u64 C_NHL2E = bc(-0.7213475204444817f);   // -0.5*log2(e)

    u64 macc[RPT] = {0ULL, 0ULL, 0ULL, 0ULL};
    u64 qacc[RPT] = {0ULL, 0ULL, 0ULL, 0ULL};

    for (int il = 0; il < IQ; ++il) {
        // record -> registers once, reused for RPT rows
        const uint4* Rq = reinterpret_cast<const uint4*>(&prm[(il * 8 + og) * RECS]);
        u64 P[RKU];
#pragma unroll
        for (int k4 = 0; k4 < 13; ++k4) {
            uint4 q = Rq[k4];
            P[2 * k4]     = pk2(q.x, q.y);
            P[2 * k4 + 1] = pk2(q.z, q.w);
        }
        const u64 l2 = P[0];

#pragma unroll
        for (int rr = 0; rr < RPT; ++rr) {
            const float2 msv = ms_sm[il][rp * RPT + rr];
            const u64 MU = bc(msv.x);
            const u64 S2 = bc(msv.y);

            // d = l2 + s2; r = 1/sqrt(d) via MUFU per half
            u64 d = f2add(l2, S2);
            unsigned dlo, dhi; upk(d, dlo, dhi);
            float rlo = rsqrtf(__uint_as_float(dlo));
            float rhi = rsqrtf(__uint_as_float(dhi));
            u64 r   = pk2(__float_as_uint(rlo), __float_as_uint(rhi));
            u64 rsq = f2mul(r, r);                   // 1/d
            const u64 ccp = f2mul(rsq, C_NHL2E);     // -log2e/(2d)

            // e_p = 2^( ccp*(mu-z_p)^2 ) via MUFU EX2 per half
            u64 e[NP];
#pragma unroll
            for (int p = 0; p < NP; ++p) {
                u64 t  = f2add(MU, P[1 + p]);        // P holds -z
                u64 t2 = f2mul(t, t);
                u64 y  = f2mul(t2, ccp);
                unsigned ylo, yhi; upk(y, ylo, yhi);
                float elo = ex2f(__uint_as_float(ylo));
                float ehi = ex2f(__uint_as_float(yhi));
                e[p] = pk2(__float_as_uint(elo), __float_as_uint(ehi));
            }

            // l*mean: e . alpha'  (alpha' = l*alpha at P[6..10])
            u64 me = f2mul(e[0], P[6]);
            me = f2fma(e[1], P[7],  me);
            me = f2fma(e[2], P[8],  me);
            me = f2fma(e[3], P[9],  me);
            me = f2fma(e[4], P[10], me);

            // l2*qKq = e^T G e  (G = l2*Kinv, off-diag doubled, lower-tri at P[11..25])
            u64 v0 = f2mul(P[11], e[0]);
            u64 v1 = f2fma(P[13], e[1], f2mul(P[12], e[0]));
            u64 v2 = f2fma(P[16], e[2], f2fma(P[15], e[1], f2mul(P[14], e[0])));
            u64 v3 = f2fma(P[20], e[3], f2fma(P[19], e[2],
                     f2fma(P[18], e[1], f2mul(P[17], e[0]))));
            u64 v4 = f2fma(P[25], e[4], f2fma(P[24], e[3],
                     f2fma(P[23], e[2], f2fma(P[22], e[1], f2mul(P[21], e[0])))));
            u64 qk = f2mul(v0, e[0]);
            qk = f2fma(v1, e[1], qk);
            qk = f2fma(v2, e[2], qk);
            qk = f2fma(v3, e[3], qk);
            qk = f2fma(v4, e[4], qk);

            macc[rr] = f2fma(me, r,   macc[rr]);   // s*mean = r * (l*mean)
            qacc[rr] = f2fma(qk, rsq, qacc[rr]);   // (1/d) * (l2 * e^T Kinv e)
        }
    }

#pragma unroll
    for (int rr = 0; rr < RPT; ++rr) {
        const int r = row0 + rp * RPT + rr;
        unsigned mlo, mhi, qlo, qhi;
        upk(macc[rr], mlo, mhi); upk(qacc[rr], qlo, qhi);
        g_part[(split * NROWS + r) * 8 + og] =
            make_float4(__uint_as_float(mlo), __uint_as_float(mhi),
                        __uint_as_float(qlo), __uint_as_float(qhi));
    }
}

// ---------------- reduce: combine the 6 i-splits ----------------
__global__ __launch_bounds__(256) void gp_reduce(float* __restrict__ out) {
    int idx = blockIdx.x * 256 + threadIdx.x;       // over NROWS*8
    if (idx >= NROWS * 8) return;
    float4 a0 = g_part[idx];
    float4 a1 = g_part[NROWS * 8 + idx];
    float4 a2 = g_part[2 * NROWS * 8 + idx];
    float4 a3 = g_part[3 * NROWS * 8 + idx];
    float4 a4 = g_part[4 * NROWS * 8 + idx];
    float4 a5 = g_part[5 * NROWS * 8 + idx];
    float mx = ((a0.x + a1.x) + (a2.x + a3.x)) + (a4.x + a5.x);
    float my = ((a0.y + a1.y) + (a2.y + a3.y)) + (a4.y + a5.y);
    float qz = ((a0.z + a1.z) + (a2.z + a3.z)) + (a4.z + a5.z);
    float qw = ((a0.w + a1.w) + (a2.w + a3.w)) + (a4.w + a5.w);
    reinterpret_cast<float2*>(out)[idx] = make_float2(mx, my);
    reinterpret_cast<float2*>(out + NROWS * OCH)[idx] =
        make_float2(fmaxf(72.0f - qz, 1e-6f), fmaxf(72.0f - qw, 1e-6f));
}

extern "C" void kernel_launch(void* const* d_in, const int* in_sizes, int n_in,
                              void* d_out, int out_size) {
    const float* xm  = (const float*)d_in[0];  // x_mean [8,32,32,8]
    const float* xv  = (const float*)d_in[1];  // x_var
    const float* z   = (const float*)d_in[2];  // [16,72,5]
    const float* h   = (const float*)d_in[3];  // [16,72,5]
    const float* rlp = (const float*)d_in[4];  // [16,72]
    float* out = (float*)d_out;                // [m (131072) | v (131072)]

    gp_pre<<<36, 32>>>(z, h, rlp);
    gp_main<<<dim3(NROWS / ROWSB, ISPLIT), 128>>>(xm, xv);
    gp_reduce<<<NROWS * 8 / 256, 256>>>(out);
}

// round 11
// speedup vs baseline: 1.1288x; 1.1288x over previous
#include <cuda_runtime.h>

// ---- problem constants ----
#define NROWS   8192      // N * OH * OW = 8*32*32
#define IDIM    72        // IC*KH*KW
#define OCH     16
#define NP      5
#define RKU     26        // u64 entries per record: l2, negz*5, alpha'*5, G*15
#define RECF    52        // floats per record in global (= RKU*2) = 13 uint4
#define RECS    60        // smem float stride: og*60%32 distinct -> conflict-free
#define ROWSB   64        // rows per CTA
#define RPT     4         // rows per thread
#define ISPLIT  6
#define IQ      12        // IDIM / ISPLIT

// global param table: [i][og][RECF] floats, og = o>>1, float2-interleaved over lane=o&1
__device__ float g_params[IDIM * 8 * RECF];
// partial sums: [split][row][og] -> float4(m.lo, m.hi, q.lo, q.hi)
__device__ float4 g_part[ISPLIT * NROWS * 8];

typedef unsigned long long u64;

// ---------------- packed f32x2 + fast-math helpers ----------------
__device__ __forceinline__ u64 pk2(unsigned lo, unsigned hi) {
    u64 d; asm("mov.b64 %0,{%1,%2};" : "=l"(d) : "r"(lo), "r"(hi)); return d;
}
__device__ __forceinline__ void upk(u64 v, unsigned& lo, unsigned& hi) {
    asm("mov.b64 {%0,%1},%2;" : "=r"(lo), "=r"(hi) : "l"(v));
}
__device__ __forceinline__ u64 bc(float f) {
    unsigned u = __float_as_uint(f); return pk2(u, u);
}
__device__ __forceinline__ u64 f2fma(u64 a, u64 b, u64 c) {
    u64 d; asm("fma.rn.f32x2 %0,%1,%2,%3;" : "=l"(d) : "l"(a), "l"(b), "l"(c)); return d;
}
__device__ __forceinline__ u64 f2mul(u64 a, u64 b) {
    u64 d; asm("mul.rn.f32x2 %0,%1,%2;" : "=l"(d) : "l"(a), "l"(b)); return d;
}
__device__ __forceinline__ u64 f2add(u64 a, u64 b) {
    u64 d; asm("add.rn.f32x2 %0,%1,%2;" : "=l"(d) : "l"(a), "l"(b)); return d;
}
__device__ __forceinline__ float ex2f(float x) {
    float y; asm("ex2.approx.f32 %0,%1;" : "=f"(y) : "f"(x)); return y;
}
__device__ __forceinline__ float lg2f(float x) {
    float y; asm("lg2.approx.f32 %0,%1;" : "=f"(y) : "f"(x)); return y;
}
__device__ __forceinline__ float rcpf(float x) {
    float y; asm("rcp.approx.f32 %0,%1;" : "=f"(y) : "f"(x)); return y;
}
// fp32 reciprocal w/ one Newton step (~1ulp)
__device__ __forceinline__ float frcp(float d) {
    float r = rcpf(d);
    return r * fmaf(-d, r, 2.0f);
}

// ---------------- precompute: shallow fp32 cofactor/Schur inverse + Newton ----------------
__global__ void gp_pre(const float* __restrict__ z,
                       const float* __restrict__ h,
                       const float* __restrict__ raw_l) {
    int pid = blockIdx.x * blockDim.x + threadIdx.x;
    if (pid >= IDIM * OCH) return;
    int o = pid / IDIM, i = pid - o * IDIM;
    int oi = o * IDIM + i;

    // softplus via MUFU: sp = ln2 * lg2(1 + 2^(x*log2e))
    float x   = raw_l[oi];
    float tx  = ex2f(x * 1.4426950408889634f);
    float spf = 0.6931471805599453f * lg2f(1.0f + tx);
    float l2f = spf * spf;
    float cK  = -0.7213475204444817f * rcpf(l2f);   // -log2e/(2 l2)

    float zz[NP], hf[NP];
#pragma unroll
    for (int p = 0; p < NP; ++p) {
        zz[p] = z[oi * NP + p];
        hf[p] = h[oi * NP + p];
    }

    // K in fp32 via ex2 (validated safe); fp64 copy only for alpha refinement
    float  Kf[NP][NP];
    double Kd[NP][NP];
#pragma unroll
    for (int p = 0; p < NP; ++p)
#pragma unroll
        for (int q = 0; q < NP; ++q) {
            float dz = zz[p] - zz[q];
            float v = ex2f(dz * dz * cK) + (p == q ? 1e-4f : 0.0f);
            Kf[p][q] = v; Kd[p][q] = (double)v;
        }

    // ---- fp32 4x4 cofactor inverse of A = Kf[0..3][0..3] (shallow) ----
#define M_(r, c) Kf[r][c]
    float s0 = M_(0,0)*M_(1,1) - M_(1,0)*M_(0,1);
    float s1 = M_(0,0)*M_(1,2) - M_(1,0)*M_(0,2);
    float s2 = M_(0,0)*M_(1,3) - M_(1,0)*M_(0,3);
    float s3 = M_(0,1)*M_(1,2) - M_(1,1)*M_(0,2);
    float s4 = M_(0,1)*M_(1,3) - M_(1,1)*M_(0,3);
    float s5 = M_(0,2)*M_(1,3) - M_(1,2)*M_(0,3);
    float c5 = M_(2,2)*M_(3,3) - M_(3,2)*M_(2,3);
    float c4 = M_(2,1)*M_(3,3) - M_(3,1)*M_(2,3);
    float c3 = M_(2,1)*M_(3,2) - M_(3,1)*M_(2,2);
    float c2 = M_(2,0)*M_(3,3) - M_(3,0)*M_(2,3);
    float c1 = M_(2,0)*M_(3,2) - M_(3,0)*M_(2,2);
    float c0 = M_(2,0)*M_(3,1) - M_(3,0)*M_(2,1);
    float det = s0*c5 - s1*c4 + s2*c3 + s3*c2 - s4*c1 + s5*c0;
    float rd = frcp(det);       // det > 0 (SPD principal minor)

    float X[NP][NP];            // becomes Kinv
    X[0][0] = ( M_(1,1)*c5 - M_(1,2)*c4 + M_(1,3)*c3) * rd;
    X[0][1] = (-M_(0,1)*c5 + M_(0,2)*c4 - M_(0,3)*c3) * rd;
    X[0][2] = ( M_(3,1)*s5 - M_(3,2)*s4 + M_(3,3)*s3) * rd;
    X[0][3] = (-M_(2,1)*s5 + M_(2,2)*s4 - M_(2,3)*s3) * rd;
    X[1][1] = ( M_(0,0)*c5 - M_(0,2)*c2 + M_(0,3)*c1) * rd;
    X[1][2] = (-M_(3,0)*s5 + M_(3,2)*s2 - M_(3,3)*s1) * rd;
    X[1][3] = ( M_(2,0)*s5 - M_(2,2)*s2 + M_(2,3)*s1) * rd;
    X[2][2] = ( M_(3,0)*s4 - M_(3,1)*s2 + M_(3,3)*s0) * rd;
    X[2][3] = (-M_(2,0)*s4 + M_(2,1)*s2 - M_(2,3)*s0) * rd;
    X[3][3] = ( M_(2,0)*s3 - M_(2,1)*s1 + M_(2,2)*s0) * rd;
    X[1][0] = X[0][1]; X[2][0] = X[0][2]; X[3][0] = X[0][3];
    X[2][1] = X[1][2]; X[3][1] = X[1][3]; X[3][2] = X[2][3];
#undef M_

    // ---- Schur complement for the 5th row/col ----
    float u4[4];
#pragma unroll
    for (int j = 0; j < 4; ++j)
        u4[j] = X[j][0]*Kf[0][4] + X[j][1]*Kf[1][4]
              + X[j][2]*Kf[2][4] + X[j][3]*Kf[3][4];
    float schur = Kf[4][4] - (u4[0]*Kf[0][4] + u4[1]*Kf[1][4]
                            + u4[2]*Kf[2][4] + u4[3]*Kf[3][4]);
    float is = frcp(schur);     // schur >= lambda_min(K) >= 1e-4
#pragma unroll
    for (int j = 0; j < 4; ++j)
#pragma unroll
        for (int k = 0; k < 4; ++k) if (k >= j)
            X[j][k] = X[j][k] + is * u4[j] * u4[k];
#pragma unroll
    for (int j = 0; j < 4; ++j) X[j][4] = -is * u4[j];
    X[4][4] = is;
#pragma unroll
    for (int j = 0; j < NP; ++j)
#pragma unroll
        for (int k = 0; k < NP; ++k) if (k < j) X[j][k] = X[k][j];

    // ---- two Newton iterations: X <- X (2I - K X)  (parallel, shallow) ----
#pragma unroll
    for (int it = 0; it < 2; ++it) {
        float T[NP][NP];    // T = 2I - K X
#pragma unroll
        for (int j = 0; j < NP; ++j)
#pragma unroll
            for (int k = 0; k < NP; ++k) {
                float s = (j == k) ? 2.0f : 0.0f;
#pragma unroll
                for (int m = 0; m < NP; ++m) s = fmaf(-Kf[j][m], X[m][k], s);
                T[j][k] = s;
            }
        float Y[NP][NP];    // Y = X T
#pragma unroll
        for (int j = 0; j < NP; ++j)
#pragma unroll
            for (int k = 0; k < NP; ++k) {
                float s = 0.0f;
#pragma unroll
                for (int m = 0; m < NP; ++m) s = fmaf(X[j][m], T[m][k], s);
                Y[j][k] = s;
            }
        // symmetrize
#pragma unroll
        for (int j = 0; j < NP; ++j)
#pragma unroll
            for (int k = 0; k < NP; ++k)
                X[j][k] = 0.5f * (Y[j][k] + Y[k][j]);
    }

    // ---- alpha = X h, one fp64-residual refinement ----
    float a0[NP];
#pragma unroll
    for (int p = 0; p < NP; ++p) {
        float s = 0.0f;
#pragma unroll
        for (int q = 0; q < NP; ++q) s = fmaf(X[p][q], hf[q], s);
        a0[p] = s;
    }
    float rf[NP];
#pragma unroll
    for (int p = 0; p < NP; ++p) {
        double s = (double)hf[p];
#pragma unroll
        for (int q = 0; q < NP; ++q) s = fma(-Kd[p][q], (double)a0[q], s);
        rf[p] = (float)s;
    }
    float al[NP];
#pragma unroll
    for (int p = 0; p < NP; ++p) {
        float s = a0[p];
#pragma unroll
        for (int q = 0; q < NP; ++q) s = fmaf(X[p][q], rf[q], s);
        al[p] = s;
    }

    // record (float2-interleaved): l2, -z*5, (l*alpha)*5, G*15
    // G[p][q] (q<=p): diag l2*X[p][p], offdiag 2*l2*X[q][p]
    int og = o >> 1, lane = o & 1;
    float* rec = g_params + (i * 8 + og) * RECF + lane;
    rec[0] = l2f;
#pragma unroll
    for (int p = 0; p < NP; ++p) rec[(1 + p) * 2] = -zz[p];
#pragma unroll
    for (int p = 0; p < NP; ++p) rec[(6 + p) * 2] = spf * al[p];
#pragma unroll
    for (int p = 0; p < NP; ++p)
#pragma unroll
        for (int q = 0; q < NP; ++q) if (q <= p) {
            float g = l2f * X[q][p];
            if (q != p) g += g;
            rec[(11 + p * (p + 1) / 2 + q) * 2] = g;
        }
}

// ---------------- main: 6-way i-split, 4 rows/thread, EX2-based exps ----------------
__global__ __launch_bounds__(128) void gp_main(const float* __restrict__ xm,
                                               const float* __restrict__ xv) {
    __shared__ __align__(16) float2 ms_sm[IQ][ROWSB + 1];   // (mu, s2)
    __shared__ __align__(16) float  prm[IQ * 8 * RECS];

    const int tid   = threadIdx.x;
    const int row0  = blockIdx.x * ROWSB;
    const int split = blockIdx.y;
    const int i0    = split * IQ;

    // stage im2col(mu,s2) for this CTA's rows, this split's i-range
    for (int idx = tid; idx < IQ * ROWSB; idx += 128) {
        int il = idx >> 6, rlocal = idx & 63;
        int i = i0 + il;
        int c = i / 9, rem = i - c * 9;
        int kh = rem / 3, kw = rem - kh * 3;
        int r = row0 + rlocal;
        int n = r >> 10, oh = (r >> 5) & 31, ow = r & 31;
        int ih = oh + kh - 1, iw = ow + kw - 1;
        float m = 0.0f, v = 0.0f;
        if ((unsigned)ih < 32u && (unsigned)iw < 32u) {
            int g = ((n * 32 + ih) * 32 + iw) * 8 + c;
            m = xm[g]; v = xv[g];
        }
        ms_sm[il][rlocal] = make_float2(m, v);
    }
    // stage this split's param records: IQ x 8 x 13 uint4, contiguous in global
    {
        const uint4* src = reinterpret_cast<const uint4*>(g_params + i0 * 8 * RECF);
        for (int idx = tid; idx < IQ * 8 * 13; idx += 128) {
            int rrec = idx / 13, k4 = idx - rrec * 13;
            uint4 v4 = src[idx];
            *reinterpret_cast<uint4*>(&prm[rrec * RECS + 4 * k4]) = v4;
        }
    }
    __syncthreads();

    const int og = tid & 7;          // 8 o-pairs
    const int rp = tid >> 3;         // 16 row-quads -> rows rp*4 .. rp*4+3

    const u64 C_NHL2E = bc(-0.7213475204444817f);   // -0.5*log2(e)

    u64 macc[RPT] = {0ULL, 0ULL, 0ULL, 0ULL};
    u64 qacc[RPT] = {0ULL, 0ULL, 0ULL, 0ULL};

    for (int il = 0; il < IQ; ++il) {
        // record -> registers once, reused for RPT rows
        const uint4* Rq = reinterpret_cast<const uint4*>(&prm[(il * 8 + og) * RECS]);
        u64 P[RKU];
#pragma unroll
        for (int k4 = 0; k4 < 13; ++k4) {
            uint4 q = Rq[k4];
            P[2 * k4]     = pk2(q.x, q.y);
            P[2 * k4 + 1] = pk2(q.z, q.w);
        }
        const u64 l2 = P[0];

#pragma unroll
        for (int rr = 0; rr < RPT; ++rr) {
            const float2 msv = ms_sm[il][rp * RPT + rr];
            const u64 MU = bc(msv.x);
            const u64 S2 = bc(msv.y);

            // d = l2 + s2; r = 1/sqrt(d) via MUFU per half
            u64 d = f2add(l2, S2);
            unsigned dlo, dhi; upk(d, dlo, dhi);
            float rlo = rsqrtf(__uint_as_float(dlo));
            float rhi = rsqrtf(__uint_as_float(dhi));
            u64 r   = pk2(__float_as_uint(rlo), __float_as_uint(rhi));
            u64 rsq = f2mul(r, r);                   // 1/d
            const u64 ccp = f2mul(rsq, C_NHL2E);     // -log2e/(2d)

            // e_p = 2^( ccp*(mu-z_p)^2 ) via MUFU EX2 per half
            u64 e[NP];
#pragma unroll
            for (int p = 0; p < NP; ++p) {
                u64 t  = f2add(MU, P[1 + p]);        // P holds -z
                u64 t2 = f2mul(t, t);
                u64 y  = f2mul(t2, ccp);
                unsigned ylo, yhi; upk(y, ylo, yhi);
                float elo = ex2f(__uint_as_float(ylo));
                float ehi = ex2f(__uint_as_float(yhi));
                e[p] = pk2(__float_as_uint(elo), __float_as_uint(ehi));
            }

            // l*mean: e . alpha'  (alpha' = l*alpha at P[6..10])
            u64 me = f2mul(e[0], P[6]);
            me = f2fma(e[1], P[7],  me);
            me = f2fma(e[2], P[8],  me);
            me = f2fma(e[3], P[9],  me);
            me = f2fma(e[4], P[10], me);

            // l2*qKq = e^T G e  (G = l2*Kinv, off-diag doubled, lower-tri at P[11..25])
            u64 v0 = f2mul(P[11], e[0]);
            u64 v1 = f2fma(P[13], e[1], f2mul(P[12], e[0]));
            u64 v2 = f2fma(P[16], e[2], f2fma(P[15], e[1], f2mul(P[14], e[0])));
            u64 v3 = f2fma(P[20], e[3], f2fma(P[19], e[2],
                     f2fma(P[18], e[1], f2mul(P[17], e[0]))));
            u64 v4 = f2fma(P[25], e[4], f2fma(P[24], e[3],
                     f2fma(P[23], e[2], f2fma(P[22], e[1], f2mul(P[21], e[0])))));
            u64 qk = f2mul(v0, e[0]);
            qk = f2fma(v1, e[1], qk);
            qk = f2fma(v2, e[2], qk);
            qk = f2fma(v3, e[3], qk);
            qk = f2fma(v4, e[4], qk);

            macc[rr] = f2fma(me, r,   macc[rr]);   // s*mean = r * (l*mean)
            qacc[rr] = f2fma(qk, rsq, qacc[rr]);   // (1/d) * (l2 * e^T Kinv e)
        }
    }

#pragma unroll
    for (int rr = 0; rr < RPT; ++rr) {
        const int r = row0 + rp * RPT + rr;
        unsigned mlo, mhi, qlo, qhi;
        upk(macc[rr], mlo, mhi); upk(qacc[rr], qlo, qhi);
        g_part[(split * NROWS + r) * 8 + og] =
            make_float4(__uint_as_float(mlo), __uint_as_float(mhi),
                        __uint_as_float(qlo), __uint_as_float(qhi));
    }
}

// ---------------- reduce: combine the 6 i-splits ----------------
__global__ __launch_bounds__(256) void gp_reduce(float* __restrict__ out) {
    int idx = blockIdx.x * 256 + threadIdx.x;       // over NROWS*8
    if (idx >= NROWS * 8) return;
    float4 a0 = g_part[idx];
    float4 a1 = g_part[NROWS * 8 + idx];
    float4 a2 = g_part[2 * NROWS * 8 + idx];
    float4 a3 = g_part[3 * NROWS * 8 + idx];
    float4 a4 = g_part[4 * NROWS * 8 + idx];
    float4 a5 = g_part[5 * NROWS * 8 + idx];
    float mx = ((a0.x + a1.x) + (a2.x + a3.x)) + (a4.x + a5.x);
    float my = ((a0.y + a1.y) + (a2.y + a3.y)) + (a4.y + a5.y);
    float qz = ((a0.z + a1.z) + (a2.z + a3.z)) + (a4.z + a5.z);
    float qw = ((a0.w + a1.w) + (a2.w + a3.w)) + (a4.w + a5.w);
    reinterpret_cast<float2*>(out)[idx] = make_float2(mx, my);
    reinterpret_cast<float2*>(out + NROWS * OCH)[idx] =
        make_float2(fmaxf(72.0f - qz, 1e-6f), fmaxf(72.0f - qw, 1e-6f));
}

extern "C" void kernel_launch(void* const* d_in, const int* in_sizes, int n_in,
                              void* d_out, int out_size) {
    const float* xm  = (const float*)d_in[0];  // x_mean [8,32,32,8]
    const float* xv  = (const float*)d_in[1];  // x_var
    const float* z   = (const float*)d_in[2];  // [16,72,5]
    const float* h   = (const float*)d_in[3];  // [16,72,5]
    const float* rlp = (const float*)d_in[4];  // [16,72]
    float* out = (float*)d_out;                // [m (131072) | v (131072)]

    gp_pre<<<36, 32>>>(z, h, rlp);
    gp_main<<<dim3(NROWS / ROWSB, ISPLIT), 128>>>(xm, xv);
    gp_reduce<<<NROWS * 8 / 256, 256>>>(out);
}